// round 3
// baseline (speedup 1.0000x reference)
#include <cuda_runtime.h>

#define N_NODES 100000
#define N_EDGES 1600000
typedef unsigned long long u64;

// ---------------- device scratch (no allocations allowed) ----------------
__device__ float g_qkv[N_NODES * 192];   // 76.8 MB  (q|k|v interleaved per head: h*24 + {q:0-7, k:8-15, v:16-23})
__device__ float g_attn[N_NODES * 64];   // 25.6 MB  unnormalized sum of e*v
__device__ float g_denom[N_NODES * 8];   // 3.2 MB   sum of e per (node, head)
__device__ float g_x1[N_NODES * 64];     // 25.6 MB  after attention + residual + LN1
__device__ int   g_row[N_EDGES];
__device__ int   g_col[N_EDGES];
__device__ int   g_is64;

// ---------------- packed fp32x2 helpers (sm_100+) ----------------
__device__ __forceinline__ u64 fma2(u64 a, u64 b, u64 c) {
    u64 d; asm("fma.rn.f32x2 %0,%1,%2,%3;" : "=l"(d) : "l"(a), "l"(b), "l"(c)); return d;
}
__device__ __forceinline__ u64 pack2(float x, float y) {
    u64 d; asm("mov.b64 %0,{%1,%2};" : "=l"(d) : "f"(x), "f"(y)); return d;
}
__device__ __forceinline__ float2 unpack2(u64 v) {
    float2 r; asm("mov.b64 {%0,%1},%2;" : "=f"(r.x), "=f"(r.y) : "l"(v)); return r;
}

// ---------------- edge-index dtype detection + conversion ----------------
__global__ void detect_kernel(const void* ei) {
    if (threadIdx.x == 0 && blockIdx.x == 0) {
        const long long* p = (const long long*)ei;
        int is64 = 1;
        for (int i = 0; i < 64; i++) {
            long long v = p[i];
            if (v < 0 || v >= N_NODES) { is64 = 0; break; }
        }
        g_is64 = is64;
    }
}

__global__ void convert_kernel(const void* ei) {
    int i = blockIdx.x * blockDim.x + threadIdx.x;
    if (i >= N_EDGES) return;
    if (g_is64) {
        const long long* p = (const long long*)ei;
        g_row[i] = (int)p[i];
        g_col[i] = (int)p[N_EDGES + i];
    } else {
        const int* p = (const int*)ei;
        g_row[i] = p[i];
        g_col[i] = p[N_EDGES + i];
    }
}

__global__ void zero_kernel() {
    int i = blockIdx.x * blockDim.x + threadIdx.x;
    if (i < N_NODES * 64) g_attn[i] = 0.f;
    if (i < N_NODES * 8)  g_denom[i] = 0.f;
}

// ---------------- qkv GEMM: x[100k,64] @ W[64,192] + b ----------------
// blockDim=192. 32 nodes/CTA. Thread = 48 col-groups x 4 m-pair-groups.
// Each thread: 4 strided cols (cg + 48k), 4 node-pairs packed in f32x2.
__global__ __launch_bounds__(192) void qkv_kernel(const float* __restrict__ x,
                                                  const float* __restrict__ w,
                                                  const float* __restrict__ bias) {
    extern __shared__ float sm[];
    float* ws = sm;            // 64*192 = 12288 floats
    float* xs = sm + 12288;    // transposed x tile [64][34] (pad 2)
    int tid = threadIdx.x;
    for (int i = tid; i < 3072; i += 192) ((float4*)ws)[i] = ((const float4*)w)[i];
    int n0 = blockIdx.x * 32;
    for (int idx = tid; idx < 2048; idx += 192) {
        int m = idx >> 6, i = idx & 63;
        xs[i * 34 + m] = x[(n0 + m) * 64 + i];
    }
    __syncthreads();
    int cg = tid % 48, mg = tid / 48;
    u64 acc[4][4];
#pragma unroll
    for (int k = 0; k < 4; k++) {
        float bv = bias[cg + 48 * k];
        u64 bp = pack2(bv, bv);
#pragma unroll
        for (int mp = 0; mp < 4; mp++) acc[mp][k] = bp;
    }
#pragma unroll 8
    for (int i = 0; i < 64; i++) {
        u64 xp[4];
#pragma unroll
        for (int mp = 0; mp < 4; mp++) xp[mp] = *(const u64*)&xs[i * 34 + (mg * 4 + mp) * 2];
#pragma unroll
        for (int k = 0; k < 4; k++) {
            float wv = ws[i * 192 + cg + 48 * k];
            u64 wp = pack2(wv, wv);
#pragma unroll
            for (int mp = 0; mp < 4; mp++) acc[mp][k] = fma2(xp[mp], wp, acc[mp][k]);
        }
    }
#pragma unroll
    for (int mp = 0; mp < 4; mp++) {
        int m = n0 + (mg * 4 + mp) * 2;
#pragma unroll
        for (int k = 0; k < 4; k++) {
            float2 v = unpack2(acc[mp][k]);
            g_qkv[m * 192 + cg + 48 * k] = v.x;
            g_qkv[(m + 1) * 192 + cg + 48 * k] = v.y;
        }
    }
}

// ---------------- edge phase: single pass, no segment-max needed ----------------
// alpha std ~0.12 so exp() never overflows; max-subtraction cancels exactly in
// the softmax quotient. 8 threads per edge (one per head).
__global__ __launch_bounds__(256) void edge_kernel() {
    int t = blockIdx.x * 256 + threadIdx.x;
    int e = t >> 3, h = t & 7;
    if (e >= N_EDGES) return;
    int r = g_row[e], c = g_col[e];
    const float4* qp = (const float4*)(g_qkv + r * 192 + h * 24);
    const float4* kp = (const float4*)(g_qkv + c * 192 + h * 24 + 8);
    float4 q0 = qp[0], q1 = qp[1];
    float4 k0 = kp[0], k1 = kp[1];
    float d = q0.x * k0.x + q0.y * k0.y + q0.z * k0.z + q0.w * k0.w
            + q1.x * k1.x + q1.y * k1.y + q1.z * k1.z + q1.w * k1.w;
    float ev = __expf(d * 0.125f);  // scale = EMBED^-0.5 = 1/8
    atomicAdd(g_denom + r * 8 + h, ev);
    const float4* vp = (const float4*)(g_qkv + c * 192 + h * 24 + 16);
    float4 v0 = vp[0], v1 = vp[1];
    float4 a0 = make_float4(ev * v0.x, ev * v0.y, ev * v0.z, ev * v0.w);
    float4 a1 = make_float4(ev * v1.x, ev * v1.y, ev * v1.z, ev * v1.w);
    atomicAdd((float4*)(g_attn + r * 64 + h * 8), a0);      // vectorized reduction (sm_90+)
    atomicAdd((float4*)(g_attn + r * 64 + h * 8 + 4), a1);
}

// ---------------- epilogue 1: out = LN1(x + attn/denom) -> g_x1 ----------------
__global__ __launch_bounds__(256) void epi1_kernel(const float* __restrict__ x,
                                                   const float* __restrict__ g,
                                                   const float* __restrict__ b) {
    int gw = (blockIdx.x * 256 + threadIdx.x) >> 5;
    int lane = threadIdx.x & 31;
    if (gw >= N_NODES) return;
    int base = gw * 64;
    float a1 = g_attn[base + lane]      / g_denom[gw * 8 + (lane >> 3)];
    float a2 = g_attn[base + 32 + lane] / g_denom[gw * 8 + 4 + (lane >> 3)];
    float z1 = x[base + lane] + a1;
    float z2 = x[base + 32 + lane] + a2;
    float s = z1 + z2, q = z1 * z1 + z2 * z2;
#pragma unroll
    for (int o = 16; o; o >>= 1) {
        s += __shfl_xor_sync(0xffffffffu, s, o);
        q += __shfl_xor_sync(0xffffffffu, q, o);
    }
    float mean = s * (1.f / 64.f);
    float rstd = rsqrtf(q * (1.f / 64.f) - mean * mean + 1e-5f);
    g_x1[base + lane]      = (z1 - mean) * rstd * g[lane] + b[lane];
    g_x1[base + 32 + lane] = (z2 - mean) * rstd * g[lane + 32] + b[lane + 32];
}

// ---------------- fused FFN: out = LN2(x1 + relu(x1@W1+b1)@W2+b2) ----------------
// Persistent (grid=148): W1+W2 (128KB) loaded into smem once per CTA.
// 32 nodes/tile; f32x2 packing over node pairs in both GEMM phases.
__global__ __launch_bounds__(256) void ffn_kernel(const float* __restrict__ w1,
                                                  const float* __restrict__ b1,
                                                  const float* __restrict__ w2,
                                                  const float* __restrict__ b2,
                                                  const float* __restrict__ lg,
                                                  const float* __restrict__ lb,
                                                  float* __restrict__ out) {
    extern __shared__ float sm[];
    float* w1s = sm;             // 16384
    float* w2s = sm + 16384;     // 16384
    float* xs  = sm + 32768;     // [64][34]  x1 tile transposed
    float* hs  = sm + 34944;     // [256][34] hidden transposed
    float* zs  = sm + 43648;     // [32][65]  pre-LN values
    int tid = threadIdx.x;
    for (int i = tid; i < 4096; i += 256) {
        ((float4*)w1s)[i] = ((const float4*)w1)[i];
        ((float4*)w2s)[i] = ((const float4*)w2)[i];
    }
    int cg = tid & 63, mg = tid >> 6;    // phase 1 mapping
    int cg2 = tid & 15, mg2 = tid >> 4;  // phase 2 mapping
    int wid = tid >> 5, lane = tid & 31;
    u64 b1p[4], b2p[4];
#pragma unroll
    for (int k = 0; k < 4; k++) { float bv = b1[cg + 64 * k];  b1p[k] = pack2(bv, bv); }
#pragma unroll
    for (int k = 0; k < 4; k++) { float bv = b2[cg2 + 16 * k]; b2p[k] = pack2(bv, bv); }
    float lgA = lg[lane], lgB = lg[lane + 32], lbA = lb[lane], lbB = lb[lane + 32];
    __syncthreads();

    for (int tile = blockIdx.x; tile < 3125; tile += gridDim.x) {
        int n0 = tile * 32;
        for (int idx = tid; idx < 2048; idx += 256) {
            int m = idx >> 6, i = idx & 63;
            xs[i * 34 + m] = g_x1[(n0 + m) * 64 + i];
        }
        __syncthreads();
        // ---- phase 1: h = relu(x1 @ W1 + b1), stored transposed hs[j][m] ----
        u64 acc[4][4];
#pragma unroll
        for (int mp = 0; mp < 4; mp++)
#pragma unroll
            for (int k = 0; k < 4; k++) acc[mp][k] = b1p[k];
#pragma unroll 8
        for (int i = 0; i < 64; i++) {
            u64 xp[4];
#pragma unroll
            for (int mp = 0; mp < 4; mp++) xp[mp] = *(const u64*)&xs[i * 34 + (mg * 4 + mp) * 2];
#pragma unroll
            for (int k = 0; k < 4; k++) {
                float wv = w1s[i * 256 + cg + 64 * k];
                u64 wp = pack2(wv, wv);
#pragma unroll
                for (int mp = 0; mp < 4; mp++) acc[mp][k] = fma2(xp[mp], wp, acc[mp][k]);
            }
        }
#pragma unroll
        for (int mp = 0; mp < 4; mp++)
#pragma unroll
            for (int k = 0; k < 4; k++) {
                float2 v = unpack2(acc[mp][k]);
                v.x = fmaxf(v.x, 0.f); v.y = fmaxf(v.y, 0.f);
                *(float2*)&hs[(cg + 64 * k) * 34 + (mg * 4 + mp) * 2] = v;
            }
        __syncthreads();
        // ---- phase 2: y = h @ W2 + b2; z = y + x1 ----
        u64 a2[4];
#pragma unroll
        for (int k = 0; k < 4; k++) a2[k] = b2p[k];
#pragma unroll 8
        for (int j = 0; j < 256; j++) {
            u64 hp = *(const u64*)&hs[j * 34 + mg2 * 2];
#pragma unroll
            for (int k = 0; k < 4; k++) {
                float wv = w2s[j * 64 + cg2 + 16 * k];
                a2[k] = fma2(hp, pack2(wv, wv), a2[k]);
            }
        }
        int m0 = mg2 * 2;
#pragma unroll
        for (int k = 0; k < 4; k++) {
            float2 v = unpack2(a2[k]);
            int c = cg2 + 16 * k;
            zs[m0 * 65 + c]       = v.x + xs[c * 34 + m0];
            zs[(m0 + 1) * 65 + c] = v.y + xs[c * 34 + m0 + 1];
        }
        __syncthreads();
        // ---- LN2: one warp per node (4 nodes per warp) ----
#pragma unroll
        for (int mm = 0; mm < 4; mm++) {
            int m = wid * 4 + mm;
            float z1 = zs[m * 65 + lane], z2 = zs[m * 65 + lane + 32];
            float s = z1 + z2, q = z1 * z1 + z2 * z2;
#pragma unroll
            for (int o = 16; o; o >>= 1) {
                s += __shfl_xor_sync(0xffffffffu, s, o);
                q += __shfl_xor_sync(0xffffffffu, q, o);
            }
            float mean = s * (1.f / 64.f);
            float rstd = rsqrtf(q * (1.f / 64.f) - mean * mean + 1e-5f);
            out[(n0 + m) * 64 + lane]      = (z1 - mean) * rstd * lgA + lbA;
            out[(n0 + m) * 64 + lane + 32] = (z2 - mean) * rstd * lgB + lbB;
        }
        __syncthreads();
    }
}

// ---------------- launch ----------------
extern "C" void kernel_launch(void* const* d_in, const int* in_sizes, int n_in,
                              void* d_out, int out_size) {
    const float* x      = (const float*)d_in[0];
    const void*  ei     = d_in[1];
    const float* attn_w = (const float*)d_in[2];
    const float* attn_b = (const float*)d_in[3];
    const float* w1     = (const float*)d_in[4];
    const float* b1     = (const float*)d_in[5];
    const float* w2     = (const float*)d_in[6];
    const float* b2     = (const float*)d_in[7];
    const float* l1g    = (const float*)d_in[8];
    const float* l1b    = (const float*)d_in[9];
    const float* l2g    = (const float*)d_in[10];
    const float* l2b    = (const float*)d_in[11];
    float* out = (float*)d_out;

    cudaFuncSetAttribute(qkv_kernel, cudaFuncAttributeMaxDynamicSharedMemorySize, 57856);
    cudaFuncSetAttribute(ffn_kernel, cudaFuncAttributeMaxDynamicSharedMemorySize, 182912);

    detect_kernel<<<1, 32>>>(ei);
    convert_kernel<<<(N_EDGES + 255) / 256, 256>>>(ei);
    zero_kernel<<<(N_NODES * 64 + 255) / 256, 256>>>();
    qkv_kernel<<<3125, 192, 57856>>>(x, attn_w, attn_b);
    edge_kernel<<<(N_EDGES * 8) / 256, 256>>>();
    epi1_kernel<<<(N_NODES + 7) / 8, 256>>>(x, l1g, l1b);
    ffn_kernel<<<148, 256, 182912>>>(w1, b1, w2, b2, l2g, l2b, out);
}

// round 4
// speedup vs baseline: 2.0207x; 2.0207x over previous
#include <cuda_runtime.h>

#define N_NODES 100000
#define N_EDGES 1600000
#define N_PAD   100032                       // padded node rows for tile overrun
#define NBLK    ((N_NODES + 255) / 256)      // 391 scan blocks
typedef unsigned long long u64;

// ---------------- device scratch (no allocations allowed) ----------------
__device__ float g_qkv[N_PAD * 192];   // q|k|v per head: h*24 + {q:0-7, k:8-15, v:16-23}
__device__ float g_x1[N_PAD * 64];     // after attention + residual + LN1
__device__ int   g_row[N_EDGES];
__device__ int   g_col[N_EDGES];
__device__ int   g_ecol[N_EDGES];      // CSR column list
__device__ int   g_cnt[N_NODES];
__device__ int   g_pos[N_NODES];
__device__ int   g_start[N_NODES];
__device__ int   g_bsum[NBLK + 1];
__device__ int   g_is64;

// ---------------- packed fp32x2 helpers (sm_100+) ----------------
__device__ __forceinline__ u64 fma2(u64 a, u64 b, u64 c) {
    u64 d; asm("fma.rn.f32x2 %0,%1,%2,%3;" : "=l"(d) : "l"(a), "l"(b), "l"(c)); return d;
}
__device__ __forceinline__ u64 pack2(float x, float y) {
    u64 d; asm("mov.b64 %0,{%1,%2};" : "=l"(d) : "f"(x), "f"(y)); return d;
}
__device__ __forceinline__ float2 unpack2(u64 v) {
    float2 r; asm("mov.b64 {%0,%1},%2;" : "=f"(r.x), "=f"(r.y) : "l"(v)); return r;
}

// ---------------- edge-index dtype detection ----------------
__global__ void detect_kernel(const void* ei) {
    if (threadIdx.x == 0 && blockIdx.x == 0) {
        const long long* p = (const long long*)ei;
        int is64 = 1;
        for (int i = 0; i < 64; i++) {
            long long v = p[i];
            if (v < 0 || v >= N_NODES) { is64 = 0; break; }
        }
        g_is64 = is64;
    }
}

__global__ void zero_kernel() {
    int i = blockIdx.x * blockDim.x + threadIdx.x;
    if (i < N_NODES) { g_cnt[i] = 0; g_pos[i] = 0; }
}

// convert + degree histogram
__global__ void convert_kernel(const void* ei) {
    int i = blockIdx.x * blockDim.x + threadIdx.x;
    if (i >= N_EDGES) return;
    int r, c;
    if (g_is64) {
        const long long* p = (const long long*)ei;
        r = (int)p[i]; c = (int)p[N_EDGES + i];
    } else {
        const int* p = (const int*)ei;
        r = p[i]; c = p[N_EDGES + i];
    }
    g_row[i] = r; g_col[i] = c;
    atomicAdd(&g_cnt[r], 1);
}

// ---------------- 3-kernel exclusive scan of g_cnt -> g_start ----------------
__global__ void scan1_kernel() {
    __shared__ int s[256];
    int i = blockIdx.x * 256 + threadIdx.x;
    s[threadIdx.x] = (i < N_NODES) ? g_cnt[i] : 0;
    __syncthreads();
    for (int o = 128; o; o >>= 1) {
        if (threadIdx.x < o) s[threadIdx.x] += s[threadIdx.x + o];
        __syncthreads();
    }
    if (threadIdx.x == 0) g_bsum[blockIdx.x] = s[0];
}

__global__ void scan2_kernel() {   // 1 block, 32 threads: scan NBLK block sums
    int lane = threadIdx.x;
    int off = 0;
    for (int base = 0; base < NBLK; base += 32) {
        int i = base + lane;
        int v = (i < NBLK) ? g_bsum[i] : 0;
        int orig = v;
#pragma unroll
        for (int o = 1; o < 32; o <<= 1) {
            int t = __shfl_up_sync(0xffffffffu, v, o);
            if (lane >= o) v += t;
        }
        if (i < NBLK) g_bsum[i] = off + v - orig;
        off += __shfl_sync(0xffffffffu, v, 31);
    }
}

__global__ void scan3_kernel() {
    __shared__ int s[256];
    int tid = threadIdx.x;
    int i = blockIdx.x * 256 + tid;
    int v = (i < N_NODES) ? g_cnt[i] : 0;
    s[tid] = v;
    __syncthreads();
    for (int o = 1; o < 256; o <<= 1) {   // Hillis-Steele inclusive
        int t = (tid >= o) ? s[tid - o] : 0;
        __syncthreads();
        s[tid] += t;
        __syncthreads();
    }
    if (i < N_NODES) g_start[i] = g_bsum[blockIdx.x] + s[tid] - v;
}

__global__ void scatter_kernel() {
    int i = blockIdx.x * blockDim.x + threadIdx.x;
    if (i >= N_EDGES) return;
    int r = g_row[i];
    int p = atomicAdd(&g_pos[r], 1);
    g_ecol[g_start[r] + p] = g_col[i];
}

// ---------------- qkv GEMM: x[100k,64] @ W[64,192] + b ----------------
// 64 nodes/CTA, blockDim 192: cg 48 cols-groups x mg 4, each thread 8 node-pairs x 4 cols.
__global__ __launch_bounds__(192, 3) void qkv_kernel(const float* __restrict__ x,
                                                     const float* __restrict__ w,
                                                     const float* __restrict__ bias) {
    extern __shared__ float sm[];
    float* ws = sm;            // 64*192 = 12288 floats
    float* xs = sm + 12288;    // [64 i][66 m-slots]
    int tid = threadIdx.x;
    for (int i = tid; i < 3072; i += 192) ((float4*)ws)[i] = ((const float4*)w)[i];
    int n0 = blockIdx.x * 64;
    for (int idx = tid; idx < 4096; idx += 192) {
        int m = idx >> 6, i = idx & 63;
        int r = n0 + m;
        xs[i * 66 + m] = (r < N_NODES) ? x[r * 64 + i] : 0.f;
    }
    __syncthreads();
    int cg = tid % 48, mg = tid / 48;
    u64 acc[8][4];
#pragma unroll
    for (int k = 0; k < 4; k++) {
        float bv = bias[cg + 48 * k];
        u64 bp = pack2(bv, bv);
#pragma unroll
        for (int mp = 0; mp < 8; mp++) acc[mp][k] = bp;
    }
#pragma unroll 4
    for (int i = 0; i < 64; i++) {
        u64 xp[8];
#pragma unroll
        for (int mp = 0; mp < 8; mp++) xp[mp] = *(const u64*)&xs[i * 66 + (mg * 8 + mp) * 2];
#pragma unroll
        for (int k = 0; k < 4; k++) {
            float wv = ws[i * 192 + cg + 48 * k];
            u64 wp = pack2(wv, wv);
#pragma unroll
            for (int mp = 0; mp < 8; mp++) acc[mp][k] = fma2(xp[mp], wp, acc[mp][k]);
        }
    }
#pragma unroll
    for (int mp = 0; mp < 8; mp++) {
        int m = n0 + (mg * 8 + mp) * 2;
#pragma unroll
        for (int k = 0; k < 4; k++) {
            float2 v = unpack2(acc[mp][k]);
            g_qkv[m * 192 + cg + 48 * k] = v.x;
            g_qkv[(m + 1) * 192 + cg + 48 * k] = v.y;
        }
    }
}

// ---------------- fused attention gather + normalize + residual + LN1 ----------------
// Warp per node. lane = (group g 0-3) x (head h 0-7). No atomics: register accumulation.
__global__ __launch_bounds__(256) void attn_kernel(const float* __restrict__ x,
                                                   const float* __restrict__ lg,
                                                   const float* __restrict__ lb) {
    __shared__ float sg[64], sb[64];
    int tid = threadIdx.x;
    if (tid < 64) sg[tid] = lg[tid];
    else if (tid < 128) sb[tid - 64] = lb[tid - 64];
    __syncthreads();
    int wid = tid >> 5, lane = tid & 31;
    int n = blockIdx.x * 8 + wid;
    int h = lane & 7, g = lane >> 3;
    const float* qb = g_qkv + n * 192 + h * 24;
    float4 q0 = *(const float4*)qb, q1 = *(const float4*)(qb + 4);
    float den = 0.f;
    float a[8];
#pragma unroll
    for (int j = 0; j < 8; j++) a[j] = 0.f;
    int s = g_start[n], e = s + g_cnt[n];
    for (int i = s + g; i < e; i += 4) {
        int c = g_ecol[i];
        const float4* kp = (const float4*)(g_qkv + c * 192 + h * 24 + 8);
        float4 k0 = kp[0], k1 = kp[1], v0 = kp[2], v1 = kp[3];
        float d = q0.x * k0.x + q0.y * k0.y + q0.z * k0.z + q0.w * k0.w
                + q1.x * k1.x + q1.y * k1.y + q1.z * k1.z + q1.w * k1.w;
        float ev = __expf(d * 0.125f);
        den += ev;
        a[0] += ev * v0.x; a[1] += ev * v0.y; a[2] += ev * v0.z; a[3] += ev * v0.w;
        a[4] += ev * v1.x; a[5] += ev * v1.y; a[6] += ev * v1.z; a[7] += ev * v1.w;
    }
    // reduce across the 4 edge-groups
#pragma unroll
    for (int o = 8; o <= 16; o <<= 1) {
        den += __shfl_xor_sync(0xffffffffu, den, o);
#pragma unroll
        for (int j = 0; j < 8; j++) a[j] += __shfl_xor_sync(0xffffffffu, a[j], o);
    }
    float inv = (den > 0.f) ? 1.f / den : 0.f;
    const float4* xb = (const float4*)(x + n * 64 + h * 8);
    float4 x0 = xb[0], x1v = xb[1];
    float z[8];
    z[0] = x0.x + a[0] * inv;  z[1] = x0.y + a[1] * inv;
    z[2] = x0.z + a[2] * inv;  z[3] = x0.w + a[3] * inv;
    z[4] = x1v.x + a[4] * inv; z[5] = x1v.y + a[5] * inv;
    z[6] = x1v.z + a[6] * inv; z[7] = x1v.w + a[7] * inv;
    float sum = 0.f, sq = 0.f;
#pragma unroll
    for (int j = 0; j < 8; j++) { sum += z[j]; sq += z[j] * z[j]; }
#pragma unroll
    for (int o = 1; o < 8; o <<= 1) {   // combine the 8 heads within each group
        sum += __shfl_xor_sync(0xffffffffu, sum, o);
        sq  += __shfl_xor_sync(0xffffffffu, sq, o);
    }
    float mean = sum * (1.f / 64.f);
    float rstd = rsqrtf(sq * (1.f / 64.f) - mean * mean + 1e-5f);
    if (g == 0) {
        float4 o0, o1;
        o0.x = (z[0] - mean) * rstd * sg[h * 8 + 0] + sb[h * 8 + 0];
        o0.y = (z[1] - mean) * rstd * sg[h * 8 + 1] + sb[h * 8 + 1];
        o0.z = (z[2] - mean) * rstd * sg[h * 8 + 2] + sb[h * 8 + 2];
        o0.w = (z[3] - mean) * rstd * sg[h * 8 + 3] + sb[h * 8 + 3];
        o1.x = (z[4] - mean) * rstd * sg[h * 8 + 4] + sb[h * 8 + 4];
        o1.y = (z[5] - mean) * rstd * sg[h * 8 + 5] + sb[h * 8 + 5];
        o1.z = (z[6] - mean) * rstd * sg[h * 8 + 6] + sb[h * 8 + 6];
        o1.w = (z[7] - mean) * rstd * sg[h * 8 + 7] + sb[h * 8 + 7];
        float4* ob = (float4*)(g_x1 + n * 64 + h * 8);
        ob[0] = o0; ob[1] = o1;
    }
}

// ---------------- fused FFN: out = LN2(x1 + relu(x1@W1+b1)@W2+b2) ----------------
// Persistent grid=148, 64-node tiles, weights resident in smem.
__global__ __launch_bounds__(256, 1) void ffn_kernel(const float* __restrict__ w1,
                                                     const float* __restrict__ b1,
                                                     const float* __restrict__ w2,
                                                     const float* __restrict__ b2,
                                                     const float* __restrict__ lg,
                                                     const float* __restrict__ lb,
                                                     float* __restrict__ out) {
    extern __shared__ float sm[];
    float* w1s = sm;             // 16384
    float* w2s = sm + 16384;     // 16384
    float* xs  = sm + 32768;     // [64 i][66 m] = 4224 (also reused as zs[64 m][66 c])
    float* hs  = sm + 36992;     // [256 j][66 m] = 16896
    int tid = threadIdx.x;
    for (int i = tid; i < 4096; i += 256) {
        ((float4*)w1s)[i] = ((const float4*)w1)[i];
        ((float4*)w2s)[i] = ((const float4*)w2)[i];
    }
    int cg = tid & 63, mg = tid >> 6;      // phase 1
    int cg2 = tid & 31, mg2 = tid >> 5;    // phase 2
    int wid = tid >> 5, lane = tid & 31;
    u64 b1p[4], b2p[2];
#pragma unroll
    for (int k = 0; k < 4; k++) { float bv = b1[cg + 64 * k]; b1p[k] = pack2(bv, bv); }
#pragma unroll
    for (int k = 0; k < 2; k++) { float bv = b2[cg2 + 32 * k]; b2p[k] = pack2(bv, bv); }
    float lgA = lg[lane], lgB = lg[lane + 32], lbA = lb[lane], lbB = lb[lane + 32];
    __syncthreads();

    for (int tile = blockIdx.x; tile < 1563; tile += 148) {
        int n0 = tile * 64;
        for (int idx = tid; idx < 4096; idx += 256) {
            int m = idx >> 6, i = idx & 63;
            xs[i * 66 + m] = g_x1[(n0 + m) * 64 + i];
        }
        __syncthreads();
        // ---- phase 1: h = relu(x1 @ W1 + b1) ----
        u64 acc[8][4];
#pragma unroll
        for (int mp = 0; mp < 8; mp++)
#pragma unroll
            for (int k = 0; k < 4; k++) acc[mp][k] = b1p[k];
#pragma unroll 4
        for (int i = 0; i < 64; i++) {
            u64 xp[8];
#pragma unroll
            for (int mp = 0; mp < 8; mp++) xp[mp] = *(const u64*)&xs[i * 66 + (mg * 8 + mp) * 2];
#pragma unroll
            for (int k = 0; k < 4; k++) {
                float wv = w1s[i * 256 + cg + 64 * k];
                u64 wp = pack2(wv, wv);
#pragma unroll
                for (int mp = 0; mp < 8; mp++) acc[mp][k] = fma2(xp[mp], wp, acc[mp][k]);
            }
        }
#pragma unroll
        for (int mp = 0; mp < 8; mp++)
#pragma unroll
            for (int k = 0; k < 4; k++) {
                float2 v = unpack2(acc[mp][k]);
                v.x = fmaxf(v.x, 0.f); v.y = fmaxf(v.y, 0.f);
                *(float2*)&hs[(cg + 64 * k) * 66 + (mg * 8 + mp) * 2] = v;
            }
        __syncthreads();
        // ---- phase 2: y = h @ W2 + b2 ----
        u64 a2[4][2];
#pragma unroll
        for (int mp = 0; mp < 4; mp++)
#pragma unroll
            for (int k = 0; k < 2; k++) a2[mp][k] = b2p[k];
#pragma unroll 4
        for (int j = 0; j < 256; j++) {
            u64 hp[4];
#pragma unroll
            for (int mp = 0; mp < 4; mp++) hp[mp] = *(const u64*)&hs[j * 66 + (mg2 * 4 + mp) * 2];
#pragma unroll
            for (int k = 0; k < 2; k++) {
                float wv = w2s[j * 64 + cg2 + 32 * k];
                u64 wp = pack2(wv, wv);
#pragma unroll
                for (int mp = 0; mp < 4; mp++) a2[mp][k] = fma2(hp[mp], wp, a2[mp][k]);
            }
        }
        // ---- residual (read xs to regs), then repack z into xs region as [m][c] ----
        float zr[4][2][2];
#pragma unroll
        for (int mp = 0; mp < 4; mp++)
#pragma unroll
            for (int k = 0; k < 2; k++) {
                int c = cg2 + 32 * k, m0 = (mg2 * 4 + mp) * 2;
                float2 v = unpack2(a2[mp][k]);
                zr[mp][k][0] = v.x + xs[c * 66 + m0];
                zr[mp][k][1] = v.y + xs[c * 66 + m0 + 1];
            }
        __syncthreads();
        float* zs = xs;
#pragma unroll
        for (int mp = 0; mp < 4; mp++)
#pragma unroll
            for (int k = 0; k < 2; k++) {
                int c = cg2 + 32 * k, m0 = (mg2 * 4 + mp) * 2;
                zs[m0 * 66 + c] = zr[mp][k][0];
                zs[(m0 + 1) * 66 + c] = zr[mp][k][1];
            }
        __syncthreads();
        // ---- LN2: 8 nodes per warp ----
#pragma unroll
        for (int mm = 0; mm < 8; mm++) {
            int m = wid * 8 + mm;
            float z1 = zs[m * 66 + lane], z2 = zs[m * 66 + 32 + lane];
            float s = z1 + z2, q = z1 * z1 + z2 * z2;
#pragma unroll
            for (int o = 16; o; o >>= 1) {
                s += __shfl_xor_sync(0xffffffffu, s, o);
                q += __shfl_xor_sync(0xffffffffu, q, o);
            }
            float mean = s * (1.f / 64.f);
            float rstd = rsqrtf(q * (1.f / 64.f) - mean * mean + 1e-5f);
            int n = n0 + m;
            if (n < N_NODES) {
                out[n * 64 + lane]      = (z1 - mean) * rstd * lgA + lbA;
                out[n * 64 + lane + 32] = (z2 - mean) * rstd * lgB + lbB;
            }
        }
        __syncthreads();
    }
}

// ---------------- launch ----------------
extern "C" void kernel_launch(void* const* d_in, const int* in_sizes, int n_in,
                              void* d_out, int out_size) {
    const float* x      = (const float*)d_in[0];
    const void*  ei     = d_in[1];
    const float* attn_w = (const float*)d_in[2];
    const float* attn_b = (const float*)d_in[3];
    const float* w1     = (const float*)d_in[4];
    const float* b1     = (const float*)d_in[5];
    const float* w2     = (const float*)d_in[6];
    const float* b2     = (const float*)d_in[7];
    const float* l1g    = (const float*)d_in[8];
    const float* l1b    = (const float*)d_in[9];
    const float* l2g    = (const float*)d_in[10];
    const float* l2b    = (const float*)d_in[11];
    float* out = (float*)d_out;

    cudaFuncSetAttribute(qkv_kernel, cudaFuncAttributeMaxDynamicSharedMemorySize, 66048);
    cudaFuncSetAttribute(ffn_kernel, cudaFuncAttributeMaxDynamicSharedMemorySize, 215552);

    detect_kernel<<<1, 32>>>(ei);
    zero_kernel<<<NBLK, 256>>>();
    convert_kernel<<<(N_EDGES + 255) / 256, 256>>>(ei);
    scan1_kernel<<<NBLK, 256>>>();
    scan2_kernel<<<1, 32>>>();
    scan3_kernel<<<NBLK, 256>>>();
    scatter_kernel<<<(N_EDGES + 255) / 256, 256>>>();
    qkv_kernel<<<(N_NODES + 63) / 64, 192, 66048>>>(x, attn_w, attn_b);
    attn_kernel<<<(N_NODES + 7) / 8, 256>>>(x, l1g, l1b);
    ffn_kernel<<<148, 256, 215552>>>(w1, b1, w2, b2, l2g, l2b, out);
}

// round 6
// speedup vs baseline: 2.2158x; 1.0966x over previous
#include <cuda_runtime.h>
#include <cuda_fp16.h>

#define N_NODES 100000
#define N_EDGES 1600000
#define N_PAD   100032                       // padded node rows for tile overrun
#define NBLK    ((N_NODES + 255) / 256)      // 391 scan blocks
typedef unsigned long long u64;

// ---------------- device scratch (no allocations allowed) ----------------
__device__ float  g_q[N_PAD * 64];     // fp32 Q  [n][h*8+e]
__device__ __half g_kv[N_PAD * 128];   // fp16 KV [n][h*16 + (k:0-7 | v:8-15)] -> 32B/(node,head)
__device__ float  g_x1[N_PAD * 64];    // after attention + residual + LN1
__device__ int    g_row[N_EDGES];
__device__ int    g_col[N_EDGES];
__device__ int    g_ecol[N_EDGES];     // CSR column list
__device__ int    g_cnt[N_NODES];
__device__ int    g_pos[N_NODES];
__device__ int    g_start[N_NODES];
__device__ int    g_bsum[NBLK + 1];
__device__ int    g_is64;

// ---------------- packed fp32x2 helpers (sm_100+) ----------------
__device__ __forceinline__ u64 fma2(u64 a, u64 b, u64 c) {
    u64 d; asm("fma.rn.f32x2 %0,%1,%2,%3;" : "=l"(d) : "l"(a), "l"(b), "l"(c)); return d;
}
__device__ __forceinline__ u64 pack2(float x, float y) {
    u64 d; asm("mov.b64 %0,{%1,%2};" : "=l"(d) : "f"(x), "f"(y)); return d;
}
__device__ __forceinline__ float2 unpack2(u64 v) {
    float2 r; asm("mov.b64 {%0,%1},%2;" : "=f"(r.x), "=f"(r.y) : "l"(v)); return r;
}

// ---------------- CSR init: zero counters + edge-dtype detection ----------------
__global__ void csr_init_kernel(const void* ei) {
    int i = blockIdx.x * blockDim.x + threadIdx.x;
    if (i < N_NODES) { g_cnt[i] = 0; g_pos[i] = 0; }
    if (blockIdx.x == 0 && threadIdx.x == 0) {
        const long long* p = (const long long*)ei;
        int is64 = 1;
        for (int j = 0; j < 64; j++) {
            long long v = p[j];
            if (v < 0 || v >= N_NODES) { is64 = 0; break; }
        }
        g_is64 = is64;
    }
}

// convert + degree histogram
__global__ void convert_kernel(const void* ei) {
    int i = blockIdx.x * blockDim.x + threadIdx.x;
    if (i >= N_EDGES) return;
    int r, c;
    if (g_is64) {
        const long long* p = (const long long*)ei;
        r = (int)p[i]; c = (int)p[N_EDGES + i];
    } else {
        const int* p = (const int*)ei;
        r = p[i]; c = p[N_EDGES + i];
    }
    g_row[i] = r; g_col[i] = c;
    atomicAdd(&g_cnt[r], 1);
}

// ---------------- 3-kernel exclusive scan of g_cnt -> g_start ----------------
__global__ void scan1_kernel() {
    __shared__ int s[256];
    int i = blockIdx.x * 256 + threadIdx.x;
    s[threadIdx.x] = (i < N_NODES) ? g_cnt[i] : 0;
    __syncthreads();
    for (int o = 128; o; o >>= 1) {
        if (threadIdx.x < o) s[threadIdx.x] += s[threadIdx.x + o];
        __syncthreads();
    }
    if (threadIdx.x == 0) g_bsum[blockIdx.x] = s[0];
}

__global__ void scan2_kernel() {   // 1 block, 32 threads
    int lane = threadIdx.x;
    int off = 0;
    for (int base = 0; base < NBLK; base += 32) {
        int i = base + lane;
        int v = (i < NBLK) ? g_bsum[i] : 0;
        int orig = v;
#pragma unroll
        for (int o = 1; o < 32; o <<= 1) {
            int t = __shfl_up_sync(0xffffffffu, v, o);
            if (lane >= o) v += t;
        }
        if (i < NBLK) g_bsum[i] = off + v - orig;
        off += __shfl_sync(0xffffffffu, v, 31);
    }
}

__global__ void scan3_kernel() {
    __shared__ int s[256];
    int tid = threadIdx.x;
    int i = blockIdx.x * 256 + tid;
    int v = (i < N_NODES) ? g_cnt[i] : 0;
    s[tid] = v;
    __syncthreads();
    for (int o = 1; o < 256; o <<= 1) {
        int t = (tid >= o) ? s[tid - o] : 0;
        __syncthreads();
        s[tid] += t;
        __syncthreads();
    }
    if (i < N_NODES) g_start[i] = g_bsum[blockIdx.x] + s[tid] - v;
}

__global__ void scatter_kernel() {
    int i = blockIdx.x * blockDim.x + threadIdx.x;
    if (i >= N_EDGES) return;
    int r = g_row[i];
    int p = atomicAdd(&g_pos[r], 1);
    g_ecol[g_start[r] + p] = g_col[i];
}

// ---------------- qkv GEMM: x[100k,64] @ W[64,192] + b ----------------
// 64 nodes/CTA, blockDim 192. GEMM column c: head=c/24, r=c%24 -> q(0-7) fp32,
// k(8-15) fp16, v(16-23) fp16.  (reference reshape(n,H,3*Dh) + split(axis=2))
__global__ __launch_bounds__(192, 3) void qkv_kernel(const float* __restrict__ x,
                                                     const float* __restrict__ w,
                                                     const float* __restrict__ bias) {
    extern __shared__ float sm[];
    float* ws = sm;            // 64*192
    float* xs = sm + 12288;    // [64 i][66 m-slots]
    int tid = threadIdx.x;
    for (int i = tid; i < 3072; i += 192) ((float4*)ws)[i] = ((const float4*)w)[i];
    int n0 = blockIdx.x * 64;
    for (int idx = tid; idx < 4096; idx += 192) {
        int m = idx >> 6, i = idx & 63;
        int r = n0 + m;
        xs[i * 66 + m] = (r < N_NODES) ? x[r * 64 + i] : 0.f;
    }
    __syncthreads();
    int cg = tid % 48, mg = tid / 48;
    u64 acc[8][4];
#pragma unroll
    for (int k = 0; k < 4; k++) {
        float bv = bias[cg + 48 * k];
        u64 bp = pack2(bv, bv);
#pragma unroll
        for (int mp = 0; mp < 8; mp++) acc[mp][k] = bp;
    }
#pragma unroll 4
    for (int i = 0; i < 64; i++) {
        u64 xp[8];
#pragma unroll
        for (int mp = 0; mp < 8; mp++) xp[mp] = *(const u64*)&xs[i * 66 + (mg * 8 + mp) * 2];
#pragma unroll
        for (int k = 0; k < 4; k++) {
            float wv = ws[i * 192 + cg + 48 * k];
            u64 wp = pack2(wv, wv);
#pragma unroll
            for (int mp = 0; mp < 8; mp++) acc[mp][k] = fma2(xp[mp], wp, acc[mp][k]);
        }
    }
#pragma unroll
    for (int mp = 0; mp < 8; mp++) {
        int m = n0 + (mg * 8 + mp) * 2;
#pragma unroll
        for (int k = 0; k < 4; k++) {
            int c = cg + 48 * k;
            int head = c / 24, r = c % 24;     // per-head interleave: q|k|v
            float2 v = unpack2(acc[mp][k]);
            if (r < 8) {
                int off = head * 8 + r;
                g_q[m * 64 + off] = v.x;
                g_q[(m + 1) * 64 + off] = v.y;
            } else {
                int off = head * 16 + (r - 8) + ((r < 16) ? 0 : 0) ;
                // r in [8,16): k slot (r-8); r in [16,24): v slot 8+(r-16) = r-8
                // both collapse to head*16 + (r-8)
                off = head * 16 + (r - 8);
                g_kv[m * 128 + off] = __float2half_rn(v.x);
                g_kv[(m + 1) * 128 + off] = __float2half_rn(v.y);
            }
        }
    }
}

// ---------------- fused attention gather + normalize + residual + LN1 ----------------
// Warp per node. lane = (group g 0-3) x (head h 0-7). fp16 K/V: 32B per (edge,head).
__global__ __launch_bounds__(256) void attn_kernel(const float* __restrict__ x,
                                                   const float* __restrict__ lg,
                                                   const float* __restrict__ lb) {
    __shared__ float sg[64], sb[64];
    int tid = threadIdx.x;
    if (tid < 64) sg[tid] = lg[tid];
    else if (tid < 128) sb[tid - 64] = lb[tid - 64];
    __syncthreads();
    int wid = tid >> 5, lane = tid & 31;
    int n = blockIdx.x * 8 + wid;
    int h = lane & 7, g = lane >> 3;
    const float4* qb = (const float4*)(g_q + n * 64 + h * 8);
    float4 q0 = qb[0], q1 = qb[1];
    float den = 0.f;
    float a[8];
#pragma unroll
    for (int j = 0; j < 8; j++) a[j] = 0.f;
    int s = g_start[n], e = s + g_cnt[n];
    for (int i = s + g; i < e; i += 4) {
        int c = g_ecol[i];
        const uint4* kvp = (const uint4*)(g_kv + c * 128 + h * 16);
        uint4 kr = kvp[0], vr = kvp[1];
        float2 k0 = __half22float2(*(__half2*)&kr.x);
        float2 k1 = __half22float2(*(__half2*)&kr.y);
        float2 k2 = __half22float2(*(__half2*)&kr.z);
        float2 k3 = __half22float2(*(__half2*)&kr.w);
        float d = q0.x * k0.x + q0.y * k0.y + q0.z * k1.x + q0.w * k1.y
                + q1.x * k2.x + q1.y * k2.y + q1.z * k3.x + q1.w * k3.y;
        float ev = __expf(d * 0.125f);
        den += ev;
        float2 v0 = __half22float2(*(__half2*)&vr.x);
        float2 v1 = __half22float2(*(__half2*)&vr.y);
        float2 v2 = __half22float2(*(__half2*)&vr.z);
        float2 v3 = __half22float2(*(__half2*)&vr.w);
        a[0] += ev * v0.x; a[1] += ev * v0.y; a[2] += ev * v1.x; a[3] += ev * v1.y;
        a[4] += ev * v2.x; a[5] += ev * v2.y; a[6] += ev * v3.x; a[7] += ev * v3.y;
    }
    // reduce across the 4 edge-groups
#pragma unroll
    for (int o = 8; o <= 16; o <<= 1) {
        den += __shfl_xor_sync(0xffffffffu, den, o);
#pragma unroll
        for (int j = 0; j < 8; j++) a[j] += __shfl_xor_sync(0xffffffffu, a[j], o);
    }
    float inv = (den > 0.f) ? 1.f / den : 0.f;
    const float4* xb = (const float4*)(x + n * 64 + h * 8);
    float4 x0 = xb[0], x1v = xb[1];
    float z[8];
    z[0] = x0.x + a[0] * inv;  z[1] = x0.y + a[1] * inv;
    z[2] = x0.z + a[2] * inv;  z[3] = x0.w + a[3] * inv;
    z[4] = x1v.x + a[4] * inv; z[5] = x1v.y + a[5] * inv;
    z[6] = x1v.z + a[6] * inv; z[7] = x1v.w + a[7] * inv;
    float sum = 0.f, sq = 0.f;
#pragma unroll
    for (int j = 0; j < 8; j++) { sum += z[j]; sq += z[j] * z[j]; }
#pragma unroll
    for (int o = 1; o < 8; o <<= 1) {
        sum += __shfl_xor_sync(0xffffffffu, sum, o);
        sq  += __shfl_xor_sync(0xffffffffu, sq, o);
    }
    float mean = sum * (1.f / 64.f);
    float rstd = rsqrtf(sq * (1.f / 64.f) - mean * mean + 1e-5f);
    if (g == 0) {
        float4 o0, o1;
        o0.x = (z[0] - mean) * rstd * sg[h * 8 + 0] + sb[h * 8 + 0];
        o0.y = (z[1] - mean) * rstd * sg[h * 8 + 1] + sb[h * 8 + 1];
        o0.z = (z[2] - mean) * rstd * sg[h * 8 + 2] + sb[h * 8 + 2];
        o0.w = (z[3] - mean) * rstd * sg[h * 8 + 3] + sb[h * 8 + 3];
        o1.x = (z[4] - mean) * rstd * sg[h * 8 + 4] + sb[h * 8 + 4];
        o1.y = (z[5] - mean) * rstd * sg[h * 8 + 5] + sb[h * 8 + 5];
        o1.z = (z[6] - mean) * rstd * sg[h * 8 + 6] + sb[h * 8 + 6];
        o1.w = (z[7] - mean) * rstd * sg[h * 8 + 7] + sb[h * 8 + 7];
        float4* ob = (float4*)(g_x1 + n * 64 + h * 8);
        ob[0] = o0; ob[1] = o1;
    }
}

// ---------------- fused FFN: out = LN2(x1 + relu(x1@W1+b1)@W2+b2) ----------------
__global__ __launch_bounds__(256, 1) void ffn_kernel(const float* __restrict__ w1,
                                                     const float* __restrict__ b1,
                                                     const float* __restrict__ w2,
                                                     const float* __restrict__ b2,
                                                     const float* __restrict__ lg,
                                                     const float* __restrict__ lb,
                                                     float* __restrict__ out) {
    extern __shared__ float sm[];
    float* w1s = sm;             // 16384
    float* w2s = sm + 16384;     // 16384
    float* xs  = sm + 32768;     // [64 i][66 m] (reused as zs[64 m][66 c])
    float* hs  = sm + 36992;     // [256 j][66 m]
    int tid = threadIdx.x;
    for (int i = tid; i < 4096; i += 256) {
        ((float4*)w1s)[i] = ((const float4*)w1)[i];
        ((float4*)w2s)[i] = ((const float4*)w2)[i];
    }
    int cg = tid & 63, mg = tid >> 6;
    int cg2 = tid & 31, mg2 = tid >> 5;
    int wid = tid >> 5, lane = tid & 31;
    u64 b1p[4], b2p[2];
#pragma unroll
    for (int k = 0; k < 4; k++) { float bv = b1[cg + 64 * k]; b1p[k] = pack2(bv, bv); }
#pragma unroll
    for (int k = 0; k < 2; k++) { float bv = b2[cg2 + 32 * k]; b2p[k] = pack2(bv, bv); }
    float lgA = lg[lane], lgB = lg[lane + 32], lbA = lb[lane], lbB = lb[lane + 32];
    __syncthreads();

    for (int tile = blockIdx.x; tile < 1563; tile += 148) {
        int n0 = tile * 64;
        for (int idx = tid; idx < 4096; idx += 256) {
            int m = idx >> 6, i = idx & 63;
            xs[i * 66 + m] = g_x1[(n0 + m) * 64 + i];
        }
        __syncthreads();
        u64 acc[8][4];
#pragma unroll
        for (int mp = 0; mp < 8; mp++)
#pragma unroll
            for (int k = 0; k < 4; k++) acc[mp][k] = b1p[k];
#pragma unroll 4
        for (int i = 0; i < 64; i++) {
            u64 xp[8];
#pragma unroll
            for (int mp = 0; mp < 8; mp++) xp[mp] = *(const u64*)&xs[i * 66 + (mg * 8 + mp) * 2];
#pragma unroll
            for (int k = 0; k < 4; k++) {
                float wv = w1s[i * 256 + cg + 64 * k];
                u64 wp = pack2(wv, wv);
#pragma unroll
                for (int mp = 0; mp < 8; mp++) acc[mp][k] = fma2(xp[mp], wp, acc[mp][k]);
            }
        }
#pragma unroll
        for (int mp = 0; mp < 8; mp++)
#pragma unroll
            for (int k = 0; k < 4; k++) {
                float2 v = unpack2(acc[mp][k]);
                v.x = fmaxf(v.x, 0.f); v.y = fmaxf(v.y, 0.f);
                *(float2*)&hs[(cg + 64 * k) * 66 + (mg * 8 + mp) * 2] = v;
            }
        __syncthreads();
        u64 a2[4][2];
#pragma unroll
        for (int mp = 0; mp < 4; mp++)
#pragma unroll
            for (int k = 0; k < 2; k++) a2[mp][k] = b2p[k];
#pragma unroll 4
        for (int j = 0; j < 256; j++) {
            u64 hp[4];
#pragma unroll
            for (int mp = 0; mp < 4; mp++) hp[mp] = *(const u64*)&hs[j * 66 + (mg2 * 4 + mp) * 2];
#pragma unroll
            for (int k = 0; k < 2; k++) {
                float wv = w2s[j * 64 + cg2 + 32 * k];
                u64 wp = pack2(wv, wv);
#pragma unroll
                for (int mp = 0; mp < 4; mp++) a2[mp][k] = fma2(hp[mp], wp, a2[mp][k]);
            }
        }
        float zr[4][2][2];
#pragma unroll
        for (int mp = 0; mp < 4; mp++)
#pragma unroll
            for (int k = 0; k < 2; k++) {
                int c = cg2 + 32 * k, m0 = (mg2 * 4 + mp) * 2;
                float2 v = unpack2(a2[mp][k]);
                zr[mp][k][0] = v.x + xs[c * 66 + m0];
                zr[mp][k][1] = v.y + xs[c * 66 + m0 + 1];
            }
        __syncthreads();
        float* zs = xs;
#pragma unroll
        for (int mp = 0; mp < 4; mp++)
#pragma unroll
            for (int k = 0; k < 2; k++) {
                int c = cg2 + 32 * k, m0 = (mg2 * 4 + mp) * 2;
                zs[m0 * 66 + c] = zr[mp][k][0];
                zs[(m0 + 1) * 66 + c] = zr[mp][k][1];
            }
        __syncthreads();
#pragma unroll
        for (int mm = 0; mm < 8; mm++) {
            int m = wid * 8 + mm;
            float z1 = zs[m * 66 + lane], z2 = zs[m * 66 + 32 + lane];
            float s = z1 + z2, q = z1 * z1 + z2 * z2;
#pragma unroll
            for (int o = 16; o; o >>= 1) {
                s += __shfl_xor_sync(0xffffffffu, s, o);
                q += __shfl_xor_sync(0xffffffffu, q, o);
            }
            float mean = s * (1.f / 64.f);
            float rstd = rsqrtf(q * (1.f / 64.f) - mean * mean + 1e-5f);
            int n = n0 + m;
            if (n < N_NODES) {
                out[n * 64 + lane]      = (z1 - mean) * rstd * lgA + lbA;
                out[n * 64 + lane + 32] = (z2 - mean) * rstd * lgB + lbB;
            }
        }
        __syncthreads();
    }
}

// ---------------- launch: CSR build forked onto a side stream under qkv ----------------
extern "C" void kernel_launch(void* const* d_in, const int* in_sizes, int n_in,
                              void* d_out, int out_size) {
    const float* x      = (const float*)d_in[0];
    const void*  ei     = d_in[1];
    const float* attn_w = (const float*)d_in[2];
    const float* attn_b = (const float*)d_in[3];
    const float* w1     = (const float*)d_in[4];
    const float* b1     = (const float*)d_in[5];
    const float* w2     = (const float*)d_in[6];
    const float* b2     = (const float*)d_in[7];
    const float* l1g    = (const float*)d_in[8];
    const float* l1b    = (const float*)d_in[9];
    const float* l2g    = (const float*)d_in[10];
    const float* l2b    = (const float*)d_in[11];
    float* out = (float*)d_out;

    static cudaStream_t s2 = nullptr;
    static cudaEvent_t evA = nullptr, evB = nullptr;
    if (s2 == nullptr) {
        cudaStreamCreateWithFlags(&s2, cudaStreamNonBlocking);
        cudaEventCreateWithFlags(&evA, cudaEventDisableTiming);
        cudaEventCreateWithFlags(&evB, cudaEventDisableTiming);
    }

    cudaFuncSetAttribute(qkv_kernel, cudaFuncAttributeMaxDynamicSharedMemorySize, 66048);
    cudaFuncSetAttribute(ffn_kernel, cudaFuncAttributeMaxDynamicSharedMemorySize, 215552);

    // fork: CSR build chain on s2 (independent of qkv GEMM)
    cudaEventRecord(evA, 0);
    cudaStreamWaitEvent(s2, evA, 0);
    csr_init_kernel<<<NBLK, 256, 0, s2>>>(ei);
    convert_kernel<<<(N_EDGES + 255) / 256, 256, 0, s2>>>(ei);
    scan1_kernel<<<NBLK, 256, 0, s2>>>();
    scan2_kernel<<<1, 32, 0, s2>>>();
    scan3_kernel<<<NBLK, 256, 0, s2>>>();
    scatter_kernel<<<(N_EDGES + 255) / 256, 256, 0, s2>>>();
    cudaEventRecord(evB, s2);

    // main stream: qkv GEMM overlaps with CSR build
    qkv_kernel<<<(N_NODES + 63) / 64, 192, 66048>>>(x, attn_w, attn_b);

    // join, then attention + FFN
    cudaStreamWaitEvent(0, evB, 0);
    attn_kernel<<<(N_NODES + 7) / 8, 256>>>(x, l1g, l1b);
    ffn_kernel<<<148, 256, 215552>>>(w1, b1, w2, b2, l2g, l2b, out);
}

// round 7
// speedup vs baseline: 2.2194x; 1.0016x over previous
#include <cuda_runtime.h>
#include <cuda_fp16.h>

#define N_NODES 100000
#define N_EDGES 1600000
#define N_PAD   100032                       // padded node rows for tile overrun
#define NBLK    ((N_NODES + 255) / 256)      // 391 scan blocks
typedef unsigned long long u64;

// ---------------- device scratch (no allocations allowed) ----------------
__device__ float  g_q[N_PAD * 64];     // fp32 Q  [n][h*8+e]
__device__ __half g_kv[N_PAD * 128];   // fp16 KV [n][h*16 + (k:0-7 | v:8-15)] -> 32B/(node,head)
__device__ float  g_x1[N_PAD * 64];    // after attention + residual + LN1
__device__ int    g_ecol[N_EDGES];     // CSR column list
__device__ int    g_cnt[N_NODES];
__device__ int    g_start[N_NODES];    // immutable CSR row starts (for attn)
__device__ int    g_startM[N_NODES];   // mutable copy consumed by scatter
__device__ u64    g_pack[NBLK];        // lookback state: (state<<32)|value, state 1=partial 2=inclusive
__device__ int    g_is64;

// ---------------- packed fp32x2 helpers (sm_100+) ----------------
__device__ __forceinline__ u64 fma2(u64 a, u64 b, u64 c) {
    u64 d; asm("fma.rn.f32x2 %0,%1,%2,%3;" : "=l"(d) : "l"(a), "l"(b), "l"(c)); return d;
}
__device__ __forceinline__ u64 pack2(float x, float y) {
    u64 d; asm("mov.b64 %0,{%1,%2};" : "=l"(d) : "f"(x), "f"(y)); return d;
}
__device__ __forceinline__ float2 unpack2(u64 v) {
    float2 r; asm("mov.b64 {%0,%1},%2;" : "=f"(r.x), "=f"(r.y) : "l"(v)); return r;
}

// ---------------- CSR init: zero counters + lookback flags + dtype detection ----------------
__global__ void csr_init_kernel(const void* ei) {
    int i = blockIdx.x * blockDim.x + threadIdx.x;
    if (i < N_NODES) g_cnt[i] = 0;
    if (i < NBLK)    g_pack[i] = 0ULL;
    if (i == 0) {
        const long long* p = (const long long*)ei;
        int is64 = 1;
        for (int j = 0; j < 64; j++) {
            long long v = p[j];
            if (v < 0 || v >= N_NODES) { is64 = 0; break; }
        }
        g_is64 = is64;
    }
}

// degree histogram straight off the input row list
__global__ void hist_kernel(const void* ei) {
    int i = blockIdx.x * blockDim.x + threadIdx.x;
    if (i >= N_EDGES) return;
    int r = g_is64 ? (int)((const long long*)ei)[i] : ((const int*)ei)[i];
    atomicAdd(&g_cnt[r], 1);
}

// ---------------- single-pass decoupled-lookback exclusive scan ----------------
__global__ void scan_kernel() {
    __shared__ int s[256];
    __shared__ int s_off;
    int bid = blockIdx.x, tid = threadIdx.x;
    int i = bid * 256 + tid;
    int v = (i < N_NODES) ? g_cnt[i] : 0;
    s[tid] = v;
    __syncthreads();
    for (int o = 1; o < 256; o <<= 1) {           // Hillis-Steele inclusive
        int t = (tid >= o) ? s[tid - o] : 0;
        __syncthreads();
        s[tid] += t;
        __syncthreads();
    }
    int total = s[255];
    if (tid == 0) {
        u64 st = (bid == 0) ? 2ULL : 1ULL;
        atomicExch(&g_pack[bid], (st << 32) | (unsigned)total);
        s_off = 0;
    }
    __syncthreads();
    if (bid > 0 && tid < 32) {                    // warp-parallel lookback
        int off = 0, j = bid - 1;
        for (;;) {
            int idx = j - tid;                    // lane0 = highest predecessor
            u64 p = 0; int st = 0;
            if (idx >= 0) {
                do {
                    p = *(volatile u64*)&g_pack[idx];
                    st = (int)(p >> 32);
                } while (st == 0);
            }
            unsigned inc_mask = __ballot_sync(0xffffffffu, idx >= 0 && st == 2);
            int val;
            if (inc_mask) {
                int lead = __ffs(inc_mask) - 1;   // lowest lane = highest idx w/ inclusive
                val = (tid <= lead) ? (int)(unsigned)p : 0;
#pragma unroll
                for (int o = 16; o; o >>= 1) val += __shfl_xor_sync(0xffffffffu, val, o);
                off += val;
                break;
            } else {
                val = (idx >= 0) ? (int)(unsigned)p : 0;
#pragma unroll
                for (int o = 16; o; o >>= 1) val += __shfl_xor_sync(0xffffffffu, val, o);
                off += val;
                j -= 32;
                if (j < 0) break;                 // unreachable: block0 publishes inclusive
            }
        }
        if (tid == 0) {
            atomicExch(&g_pack[bid], (2ULL << 32) | (unsigned)(off + total));
            s_off = off;
        }
    }
    __syncthreads();
    if (i < N_NODES) {
        int st = s_off + s[tid] - v;              // exclusive prefix
        g_start[i] = st;
        g_startM[i] = st;
    }
}

__global__ void scatter_kernel(const void* ei) {
    int i = blockIdx.x * blockDim.x + threadIdx.x;
    if (i >= N_EDGES) return;
    int r, c;
    if (g_is64) {
        const long long* p = (const long long*)ei;
        r = (int)p[i]; c = (int)p[N_EDGES + i];
    } else {
        const int* p = (const int*)ei;
        r = p[i]; c = p[N_EDGES + i];
    }
    int pos = atomicAdd(&g_startM[r], 1);
    g_ecol[pos] = c;
}

// ---------------- qkv GEMM: x[100k,64] @ W[64,192] + b ----------------
// 64 nodes/CTA, blockDim 192. GEMM column c: head=c/24, r=c%24 -> q(0-7) fp32,
// k/v(8-23) fp16 at head*16 + (r-8).  (reference reshape(n,H,3*Dh) + split(axis=2))
__global__ __launch_bounds__(192, 3) void qkv_kernel(const float* __restrict__ x,
                                                     const float* __restrict__ w,
                                                     const float* __restrict__ bias) {
    extern __shared__ float sm[];
    float* ws = sm;            // 64*192
    float* xs = sm + 12288;    // [64 i][66 m-slots]
    int tid = threadIdx.x;
    for (int i = tid; i < 3072; i += 192) ((float4*)ws)[i] = ((const float4*)w)[i];
    int n0 = blockIdx.x * 64;
    for (int idx = tid; idx < 4096; idx += 192) {
        int m = idx >> 6, i = idx & 63;
        int r = n0 + m;
        xs[i * 66 + m] = (r < N_NODES) ? x[r * 64 + i] : 0.f;
    }
    __syncthreads();
    int cg = tid % 48, mg = tid / 48;
    u64 acc[8][4];
#pragma unroll
    for (int k = 0; k < 4; k++) {
        float bv = bias[cg + 48 * k];
        u64 bp = pack2(bv, bv);
#pragma unroll
        for (int mp = 0; mp < 8; mp++) acc[mp][k] = bp;
    }
#pragma unroll 4
    for (int i = 0; i < 64; i++) {
        u64 xp[8];
#pragma unroll
        for (int mp = 0; mp < 8; mp++) xp[mp] = *(const u64*)&xs[i * 66 + (mg * 8 + mp) * 2];
#pragma unroll
        for (int k = 0; k < 4; k++) {
            float wv = ws[i * 192 + cg + 48 * k];
            u64 wp = pack2(wv, wv);
#pragma unroll
            for (int mp = 0; mp < 8; mp++) acc[mp][k] = fma2(xp[mp], wp, acc[mp][k]);
        }
    }
#pragma unroll
    for (int mp = 0; mp < 8; mp++) {
        int m = n0 + (mg * 8 + mp) * 2;
#pragma unroll
        for (int k = 0; k < 4; k++) {
            int c = cg + 48 * k;
            int head = c / 24, r = c % 24;     // per-head interleave: q|k|v
            float2 v = unpack2(acc[mp][k]);
            if (r < 8) {
                int off = head * 8 + r;
                g_q[m * 64 + off] = v.x;
                g_q[(m + 1) * 64 + off] = v.y;
            } else {
                int off = head * 16 + (r - 8); // k: 0-7, v: 8-15 within head
                g_kv[m * 128 + off] = __float2half_rn(v.x);
                g_kv[(m + 1) * 128 + off] = __float2half_rn(v.y);
            }
        }
    }
}

// ---------------- fused attention gather + normalize + residual + LN1 ----------------
// Warp per node. lane = (group g 0-3) x (head h 0-7). fp16 K/V: 32B per (edge,head).
__global__ __launch_bounds__(256) void attn_kernel(const float* __restrict__ x,
                                                   const float* __restrict__ lg,
                                                   const float* __restrict__ lb) {
    __shared__ float sg[64], sb[64];
    int tid = threadIdx.x;
    if (tid < 64) sg[tid] = lg[tid];
    else if (tid < 128) sb[tid - 64] = lb[tid - 64];
    __syncthreads();
    int wid = tid >> 5, lane = tid & 31;
    int n = blockIdx.x * 8 + wid;
    int h = lane & 7, g = lane >> 3;
    const float4* qb = (const float4*)(g_q + n * 64 + h * 8);
    float4 q0 = qb[0], q1 = qb[1];
    float den = 0.f;
    float a[8];
#pragma unroll
    for (int j = 0; j < 8; j++) a[j] = 0.f;
    int s = g_start[n], e = s + g_cnt[n];
    for (int i = s + g; i < e; i += 4) {
        int c = g_ecol[i];
        const uint4* kvp = (const uint4*)(g_kv + c * 128 + h * 16);
        uint4 kr = kvp[0], vr = kvp[1];
        float2 k0 = __half22float2(*(__half2*)&kr.x);
        float2 k1 = __half22float2(*(__half2*)&kr.y);
        float2 k2 = __half22float2(*(__half2*)&kr.z);
        float2 k3 = __half22float2(*(__half2*)&kr.w);
        float d = q0.x * k0.x + q0.y * k0.y + q0.z * k1.x + q0.w * k1.y
                + q1.x * k2.x + q1.y * k2.y + q1.z * k3.x + q1.w * k3.y;
        float ev = __expf(d * 0.125f);
        den += ev;
        float2 v0 = __half22float2(*(__half2*)&vr.x);
        float2 v1 = __half22float2(*(__half2*)&vr.y);
        float2 v2 = __half22float2(*(__half2*)&vr.z);
        float2 v3 = __half22float2(*(__half2*)&vr.w);
        a[0] += ev * v0.x; a[1] += ev * v0.y; a[2] += ev * v1.x; a[3] += ev * v1.y;
        a[4] += ev * v2.x; a[5] += ev * v2.y; a[6] += ev * v3.x; a[7] += ev * v3.y;
    }
    // reduce across the 4 edge-groups
#pragma unroll
    for (int o = 8; o <= 16; o <<= 1) {
        den += __shfl_xor_sync(0xffffffffu, den, o);
#pragma unroll
        for (int j = 0; j < 8; j++) a[j] += __shfl_xor_sync(0xffffffffu, a[j], o);
    }
    float inv = (den > 0.f) ? 1.f / den : 0.f;
    const float4* xb = (const float4*)(x + n * 64 + h * 8);
    float4 x0 = xb[0], x1v = xb[1];
    float z[8];
    z[0] = x0.x + a[0] * inv;  z[1] = x0.y + a[1] * inv;
    z[2] = x0.z + a[2] * inv;  z[3] = x0.w + a[3] * inv;
    z[4] = x1v.x + a[4] * inv; z[5] = x1v.y + a[5] * inv;
    z[6] = x1v.z + a[6] * inv; z[7] = x1v.w + a[7] * inv;
    float sum = 0.f, sq = 0.f;
#pragma unroll
    for (int j = 0; j < 8; j++) { sum += z[j]; sq += z[j] * z[j]; }
#pragma unroll
    for (int o = 1; o < 8; o <<= 1) {
        sum += __shfl_xor_sync(0xffffffffu, sum, o);
        sq  += __shfl_xor_sync(0xffffffffu, sq, o);
    }
    float mean = sum * (1.f / 64.f);
    float rstd = rsqrtf(sq * (1.f / 64.f) - mean * mean + 1e-5f);
    if (g == 0) {
        float4 o0, o1;
        o0.x = (z[0] - mean) * rstd * sg[h * 8 + 0] + sb[h * 8 + 0];
        o0.y = (z[1] - mean) * rstd * sg[h * 8 + 1] + sb[h * 8 + 1];
        o0.z = (z[2] - mean) * rstd * sg[h * 8 + 2] + sb[h * 8 + 2];
        o0.w = (z[3] - mean) * rstd * sg[h * 8 + 3] + sb[h * 8 + 3];
        o1.x = (z[4] - mean) * rstd * sg[h * 8 + 4] + sb[h * 8 + 4];
        o1.y = (z[5] - mean) * rstd * sg[h * 8 + 5] + sb[h * 8 + 5];
        o1.z = (z[6] - mean) * rstd * sg[h * 8 + 6] + sb[h * 8 + 6];
        o1.w = (z[7] - mean) * rstd * sg[h * 8 + 7] + sb[h * 8 + 7];
        float4* ob = (float4*)(g_x1 + n * 64 + h * 8);
        ob[0] = o0; ob[1] = o1;
    }
}

// ---------------- fused FFN: out = LN2(x1 + relu(x1@W1+b1)@W2+b2) ----------------
__global__ __launch_bounds__(256, 1) void ffn_kernel(const float* __restrict__ w1,
                                                     const float* __restrict__ b1,
                                                     const float* __restrict__ w2,
                                                     const float* __restrict__ b2,
                                                     const float* __restrict__ lg,
                                                     const float* __restrict__ lb,
                                                     float* __restrict__ out) {
    extern __shared__ float sm[];
    float* w1s = sm;             // 16384
    float* w2s = sm + 16384;     // 16384
    float* xs  = sm + 32768;     // [64 i][66 m] (reused as zs[64 m][66 c])
    float* hs  = sm + 36992;     // [256 j][66 m]
    int tid = threadIdx.x;
    for (int i = tid; i < 4096; i += 256) {
        ((float4*)w1s)[i] = ((const float4*)w1)[i];
        ((float4*)w2s)[i] = ((const float4*)w2)[i];
    }
    int cg = tid & 63, mg = tid >> 6;
    int cg2 = tid & 31, mg2 = tid >> 5;
    int wid = tid >> 5, lane = tid & 31;
    u64 b1p[4], b2p[2];
#pragma unroll
    for (int k = 0; k < 4; k++) { float bv = b1[cg + 64 * k]; b1p[k] = pack2(bv, bv); }
#pragma unroll
    for (int k = 0; k < 2; k++) { float bv = b2[cg2 + 32 * k]; b2p[k] = pack2(bv, bv); }
    float lgA = lg[lane], lgB = lg[lane + 32], lbA = lb[lane], lbB = lb[lane + 32];
    __syncthreads();

    for (int tile = blockIdx.x; tile < 1563; tile += 148) {
        int n0 = tile * 64;
        for (int idx = tid; idx < 4096; idx += 256) {
            int m = idx >> 6, i = idx & 63;
            xs[i * 66 + m] = g_x1[(n0 + m) * 64 + i];
        }
        __syncthreads();
        u64 acc[8][4];
#pragma unroll
        for (int mp = 0; mp < 8; mp++)
#pragma unroll
            for (int k = 0; k < 4; k++) acc[mp][k] = b1p[k];
#pragma unroll 4
        for (int i = 0; i < 64; i++) {
            u64 xp[8];
#pragma unroll
            for (int mp = 0; mp < 8; mp++) xp[mp] = *(const u64*)&xs[i * 66 + (mg * 8 + mp) * 2];
#pragma unroll
            for (int k = 0; k < 4; k++) {
                float wv = w1s[i * 256 + cg + 64 * k];
                u64 wp = pack2(wv, wv);
#pragma unroll
                for (int mp = 0; mp < 8; mp++) acc[mp][k] = fma2(xp[mp], wp, acc[mp][k]);
            }
        }
#pragma unroll
        for (int mp = 0; mp < 8; mp++)
#pragma unroll
            for (int k = 0; k < 4; k++) {
                float2 v = unpack2(acc[mp][k]);
                v.x = fmaxf(v.x, 0.f); v.y = fmaxf(v.y, 0.f);
                *(float2*)&hs[(cg + 64 * k) * 66 + (mg * 8 + mp) * 2] = v;
            }
        __syncthreads();
        u64 a2[4][2];
#pragma unroll
        for (int mp = 0; mp < 4; mp++)
#pragma unroll
            for (int k = 0; k < 2; k++) a2[mp][k] = b2p[k];
#pragma unroll 4
        for (int j = 0; j < 256; j++) {
            u64 hp[4];
#pragma unroll
            for (int mp = 0; mp < 4; mp++) hp[mp] = *(const u64*)&hs[j * 66 + (mg2 * 4 + mp) * 2];
#pragma unroll
            for (int k = 0; k < 2; k++) {
                float wv = w2s[j * 64 + cg2 + 32 * k];
                u64 wp = pack2(wv, wv);
#pragma unroll
                for (int mp = 0; mp < 4; mp++) a2[mp][k] = fma2(hp[mp], wp, a2[mp][k]);
            }
        }
        float zr[4][2][2];
#pragma unroll
        for (int mp = 0; mp < 4; mp++)
#pragma unroll
            for (int k = 0; k < 2; k++) {
                int c = cg2 + 32 * k, m0 = (mg2 * 4 + mp) * 2;
                float2 v = unpack2(a2[mp][k]);
                zr[mp][k][0] = v.x + xs[c * 66 + m0];
                zr[mp][k][1] = v.y + xs[c * 66 + m0 + 1];
            }
        __syncthreads();
        float* zs = xs;
#pragma unroll
        for (int mp = 0; mp < 4; mp++)
#pragma unroll
            for (int k = 0; k < 2; k++) {
                int c = cg2 + 32 * k, m0 = (mg2 * 4 + mp) * 2;
                zs[m0 * 66 + c] = zr[mp][k][0];
                zs[(m0 + 1) * 66 + c] = zr[mp][k][1];
            }
        __syncthreads();
#pragma unroll
        for (int mm = 0; mm < 8; mm++) {
            int m = wid * 8 + mm;
            float z1 = zs[m * 66 + lane], z2 = zs[m * 66 + 32 + lane];
            float s = z1 + z2, q = z1 * z1 + z2 * z2;
#pragma unroll
            for (int o = 16; o; o >>= 1) {
                s += __shfl_xor_sync(0xffffffffu, s, o);
                q += __shfl_xor_sync(0xffffffffu, q, o);
            }
            float mean = s * (1.f / 64.f);
            float rstd = rsqrtf(q * (1.f / 64.f) - mean * mean + 1e-5f);
            int n = n0 + m;
            if (n < N_NODES) {
                out[n * 64 + lane]      = (z1 - mean) * rstd * lgA + lbA;
                out[n * 64 + lane + 32] = (z2 - mean) * rstd * lgB + lbB;
            }
        }
        __syncthreads();
    }
}

// ---------------- launch: CSR build forked onto a side stream under qkv ----------------
extern "C" void kernel_launch(void* const* d_in, const int* in_sizes, int n_in,
                              void* d_out, int out_size) {
    const float* x      = (const float*)d_in[0];
    const void*  ei     = d_in[1];
    const float* attn_w = (const float*)d_in[2];
    const float* attn_b = (const float*)d_in[3];
    const float* w1     = (const float*)d_in[4];
    const float* b1     = (const float*)d_in[5];
    const float* w2     = (const float*)d_in[6];
    const float* b2     = (const float*)d_in[7];
    const float* l1g    = (const float*)d_in[8];
    const float* l1b    = (const float*)d_in[9];
    const float* l2g    = (const float*)d_in[10];
    const float* l2b    = (const float*)d_in[11];
    float* out = (float*)d_out;

    static cudaStream_t s2 = nullptr;
    static cudaEvent_t evA = nullptr, evB = nullptr;
    if (s2 == nullptr) {
        cudaStreamCreateWithFlags(&s2, cudaStreamNonBlocking);
        cudaEventCreateWithFlags(&evA, cudaEventDisableTiming);
        cudaEventCreateWithFlags(&evB, cudaEventDisableTiming);
    }

    cudaFuncSetAttribute(qkv_kernel, cudaFuncAttributeMaxDynamicSharedMemorySize, 66048);
    cudaFuncSetAttribute(ffn_kernel, cudaFuncAttributeMaxDynamicSharedMemorySize, 215552);

    // fork: CSR build chain on s2 (independent of qkv GEMM)
    cudaEventRecord(evA, 0);
    cudaStreamWaitEvent(s2, evA, 0);
    csr_init_kernel<<<NBLK, 256, 0, s2>>>(ei);
    hist_kernel<<<(N_EDGES + 255) / 256, 256, 0, s2>>>(ei);
    scan_kernel<<<NBLK, 256, 0, s2>>>();
    scatter_kernel<<<(N_EDGES + 255) / 256, 256, 0, s2>>>(ei);
    cudaEventRecord(evB, s2);

    // main stream: qkv GEMM overlaps with CSR build
    qkv_kernel<<<(N_NODES + 63) / 64, 192, 66048>>>(x, attn_w, attn_b);

    // join, then attention + FFN
    cudaStreamWaitEvent(0, evB, 0);
    attn_kernel<<<(N_NODES + 7) / 8, 256>>>(x, l1g, l1b);
    ffn_kernel<<<148, 256, 215552>>>(w1, b1, w2, b2, l2g, l2b, out);
}